// round 8
// baseline (speedup 1.0000x reference)
#include <cuda_runtime.h>
#include <math.h>

#define NT 365
#define NTP 372          // padded (chunk pipeline reads up to +17)
#define NCHUNK 23
#define CH 16
#define BPITCH 68        // 4-float-aligned rows for float4 reduce
#define NS 1024
#define NH 64
#define NG 32
#define NW 514           // NH*8 + 2
#define NK 11            // 10 derived constants + qb row

// Derived per-(site,h) constants: [NS][NK][NH]
__device__ float g_c[NS * NK * NH];

__device__ __forceinline__ float sigm(float x) { return 1.0f / (1.0f + expf(-x)); }

// ---------------------------------------------------------------------------
// Gates kernel: 128 blocks x 256 threads, 8 sites/block, 1 warp per site
// (2 h per lane). fc_w staged in padded smem (pitch 33, conflict-free) in two
// passes; each site-warp computes its dots + qb from smem, then activations,
// softmax, and writes 11 derived-constant rows to g_c.
// ---------------------------------------------------------------------------
__global__ void __launch_bounds__(256)
gates_kernel(const float* __restrict__ xc,
             const float* __restrict__ fc_w,
             const float* __restrict__ fc_b) {
    __shared__ float sw[258 * 33];           // 34 KB

    const int tid  = threadIdx.x;
    const int lane = tid & 31;
    const int w    = tid >> 5;
    const int s    = blockIdx.x * 8 + w;

    float xr[32];
    {
        const float4* xc4 = reinterpret_cast<const float4*>(xc + s * NG);
        #pragma unroll
        for (int q = 0; q < 8; ++q) {
            float4 v = xc4[q];
            xr[4*q] = v.x; xr[4*q+1] = v.y; xr[4*q+2] = v.z; xr[4*q+3] = v.w;
        }
    }

    float wv[2][8];
    float qbv = 0.0f;

    #pragma unroll
    for (int pass = 0; pass < 2; ++pass) {
        const int rbase = pass ? 256 : 0;
        const int rcnt  = pass ? 258 : 256;
        __syncthreads();
        for (int i = tid; i < rcnt * NG; i += 256) {
            int r = i >> 5, k = i & 31;
            sw[r * 33 + k] = fc_w[(rbase + r) * NG + k];
        }
        __syncthreads();
        const int clo = pass ? 4 : 0;
        #pragma unroll
        for (int cc = 0; cc < 4; ++cc) {
            const int c = clo + cc;
            #pragma unroll
            for (int u = 0; u < 2; ++u) {
                const int j = c * 64 + lane + u * 32;   // pass0: <256, pass1: 256..511
                const float* row = sw + (j - rbase) * 33;
                float acc = 0.0f;
                #pragma unroll
                for (int k = 0; k < NG; ++k) acc += xr[k] * row[k];
                wv[u][c] = acc + fc_b[j];
            }
        }
        if (pass == 1) {                                 // qb row j = 513
            const float* row = sw + (513 - 256) * 33;
            float acc = 0.0f;
            #pragma unroll
            for (int k = 0; k < NG; ++k) acc += xr[k] * row[k];
            qbv = fmaxf(acc + fc_b[513], 0.0f) * (1.0f / 64.0f);
        }
    }

    float gm[2], nge[2], go[2], gl[2], araw[2], gb[2], kb[2], gi[2];
    #pragma unroll
    for (int u = 0; u < 2; ++u) {
        gm[u]   = expf(wv[u][0]) + 1.0f;
        nge[u]  = -2.0f * sigm(wv[u][1]);
        go[u]   = sigm(wv[u][2]);
        gl[u]   = expf(2.0f * wv[u][3]);
        araw[u] = wv[u][4];
        gb[u]   = sigm(wv[u][5]);
        kb[u]   = sigm(wv[u][6]) * 0.1f;
        gi[u]   = sigm(wv[u][7]);
    }
    float m = fmaxf(araw[0], araw[1]);
    #pragma unroll
    for (int o = 16; o; o >>= 1) m = fmaxf(m, __shfl_xor_sync(0xffffffffu, m, o));
    float e0 = expf(araw[0] - m), e1 = expf(araw[1] - m);
    float ssum = e0 + e1;
    #pragma unroll
    for (int o = 16; o; o >>= 1) ssum += __shfl_xor_sync(0xffffffffu, ssum, o);
    float inv = 1.0f / ssum;
    float ga[2] = { e0 * inv, e1 * inv };

    float* base = g_c + s * NK * NH;
    #pragma unroll
    for (int u = 0; u < 2; ++u) {
        const int h = lane + u * 32;
        base[0*NH + h]  = gm[u];
        base[1*NH + h]  = nge[u];
        base[2*NH + h]  = go[u];
        base[3*NH + h]  = gl[u];
        base[4*NH + h]  = ga[u];
        base[5*NH + h]  = go[u] * (1.0f - gb[u]) * ga[u] - ga[u];  // chc
        base[6*NH + h]  = kb[u] * ga[u];                           // cg
        base[7*NH + h]  = go[u] * gb[u];                           // gogb
        base[8*NH + h]  = 1.0f - kb[u];                            // kb1
        base[9*NH + h]  = qbv;                                     // qb
        base[10*NH + h] = gi[u];                                   // gi
    }
}

// ---------------------------------------------------------------------------
// Scan kernel: 1024 blocks x 64 threads (2 warps/site, 1 h per lane).
// Slim prologue; chunked loop with 2-deep software-pipelined forcing LDS,
// y buffered in registers + burst-stored, float4 tree-reduce per chunk.
// ---------------------------------------------------------------------------
__global__ void __launch_bounds__(64)
scan_kernel(const float* __restrict__ x, float* __restrict__ out) {
    __shared__ float4 sForc[NTP];              // 5952 B
    __shared__ float  sBuf[2][CH * BPITCH];    // 8704 B

    const int tid = threadIdx.x;
    const int s   = blockIdx.x;

    const float4* x4 = reinterpret_cast<const float4*>(x);
    for (int t = tid; t < NTP; t += 64) {
        float4 o = make_float4(0.f, 0.f, 0.f, 0.f);
        if (t < NT) {
            float4 xi = x4[t * NS + s];
            float P = xi.x, E = xi.y, T1 = xi.z, T2 = xi.w;
            float Ta = (T1 + T2) * 0.5f;
            bool valid  = (T1 < 0.0f) && (T2 > 0.0f);
            float denom = valid ? (T2 - T1) : 1.0f;
            float ratio = valid ? (T1 + T2) / denom : 0.0f;
            ratio = fminf(fmaxf(ratio, -0.999999f), 0.999999f);
            float rP = 1.0f - acosf(ratio) / 3.1415f;
            if (T1 >= 0.0f) rP = 1.0f;
            if (T2 <= 0.0f) rP = 0.0f;
            o.x = (1.0f - rP) * P;   // Ps
            o.y = rP * P;            // Pl
            o.z = Ta;
            o.w = E;
        }
        sForc[t] = o;
    }

    const float* base = g_c + s * NK * NH;
    const float gm   = base[0*NH + tid];
    const float nge  = base[1*NH + tid];
    const float go   = base[2*NH + tid];
    const float gl   = base[3*NH + tid];
    const float ga   = base[4*NH + tid];
    const float chc  = base[5*NH + tid];
    const float cg   = base[6*NH + tid];
    const float gogb = base[7*NH + tid];
    const float kb1  = base[8*NH + tid];
    const float qb   = base[9*NH + tid];
    const float gi   = base[10*NH + tid];

    __syncthreads();

    float S0 = 0.0f, H0 = 0.0f, G0 = 0.0f;
    const int rt = tid >> 2;
    const int rq = tid & 3;

    for (int c = 0; c < NCHUNK; ++c) {
        float* buf = sBuf[c & 1];
        const float4* fp = sForc + c * CH;
        float4 f0 = fp[0];
        float4 f1 = fp[1];
        float yv[CH];
        #pragma unroll
        for (int tt = 0; tt < CH; ++tt) {
            float4 f = f0; f0 = f1; f1 = fp[tt + 2];   // 2-deep pipeline
            float mt  = fmaxf(f.z * gm, 0.0f);
            float Sm  = fminf(S0, mt);
            float At  = fmaf(f.w, nge, f.y * gi);      // Pl*gi - E*ge
            float H   = fmaxf(H0 + Sm + At, 0.0f);
            float Hc  = fminf(H, gl);
            float t1  = fmaf(-go, Hc, H);
            float g2  = fmaf(Hc, gogb, G0);
            H0 = fminf(t1, gl);
            G0 = g2 * kb1;
            S0 = (S0 - Sm) + f.x;
            float y = H * ga;
            y = fmaf(Hc, chc, y);
            y = fmaf(g2, cg, y);
            yv[tt] = y;
        }
        #pragma unroll
        for (int tt = 0; tt < CH; ++tt)
            buf[tt * BPITCH + tid] = yv[tt];           // burst, conflict-free
        __syncthreads();
        const float4* rr4 = reinterpret_cast<const float4*>(
            sBuf[c & 1] + rt * BPITCH + rq * 16);
        float4 v0 = rr4[0], v1 = rr4[1], v2 = rr4[2], v3 = rr4[3];
        float p = (((v0.x + v0.y) + (v0.z + v0.w)) + ((v1.x + v1.y) + (v1.z + v1.w)))
                + (((v2.x + v2.y) + (v2.z + v2.w)) + ((v3.x + v3.y) + (v3.z + v3.w)));
        p += __shfl_xor_sync(0xffffffffu, p, 1);
        p += __shfl_xor_sync(0xffffffffu, p, 2);
        const int tg = c * CH + rt;
        if (rq == 0 && tg < NT) out[tg * NS + s] = p + qb;
    }
}

// ---------------------------------------------------------------------------
extern "C" void kernel_launch(void* const* d_in, const int* in_sizes, int n_in,
                              void* d_out, int out_size) {
    const float* x    = (const float*)d_in[0];   // [NT, NS, 4]
    const float* xc   = (const float*)d_in[1];   // [NS, NG]
    const float* fc_w = (const float*)d_in[2];   // [NW, NG]
    const float* fc_b = (const float*)d_in[3];   // [NW]
    float* out = (float*)d_out;                  // [NT, NS]

    gates_kernel<<<NS / 8, 256>>>(xc, fc_w, fc_b);
    scan_kernel<<<NS, 64>>>(x, out);
}

// round 9
// speedup vs baseline: 1.2169x; 1.2169x over previous
#include <cuda_runtime.h>
#include <math.h>

#define NT 365
#define NTP 368          // 23 chunks of 16
#define NCHUNK 23
#define CH 16
#define RPITCH 36        // reduce-buffer row pitch (conflict-free float4 reads)
#define NS 1024
#define NH 64
#define NG 32
#define NW 514           // NH*8 + 2
#define NK 10            // derived-constant rows in g_c

// Derived per-(site,h) constants [NS][NK][NH], qb [NS], partial sums [NT][NS]
__device__ float g_c[NS * NK * NH];
__device__ float g_qb[NS];
__device__ float g_pA[NT * NS];
__device__ float g_pB[NT * NS];

__device__ __forceinline__ float sigm(float x) { return 1.0f / (1.0f + expf(-x)); }

// ---------------------------------------------------------------------------
// Gates: 256 blocks x 256 threads, 4 sites/block (2 warps per site).
// Coalesced warp-cooperative GEMV (1 LDG.128 covers 4 consecutive fc_w rows'
// quarters; octet shfl reduce). Then activations + cross-warp softmax and the
// 10 derived-constant rows + qb are written out.
// ---------------------------------------------------------------------------
__global__ void __launch_bounds__(256)
gates_kernel(const float* __restrict__ xc,
             const float* __restrict__ fc_w,
             const float* __restrict__ fc_b) {
    __shared__ float  sW[4][512];
    __shared__ float4 sXc4[4][8];
    __shared__ float  sMax[4][2], sSum[4][2];

    const int tid  = threadIdx.x;
    const int warp = tid >> 5;        // 0..7
    const int lane = tid & 31;
    const int si   = warp >> 1;       // site within block 0..3
    const int w2   = warp & 1;        // half (h-half AND row-half role)
    const int s    = blockIdx.x * 4 + si;

    if (tid < 32) {                    // 4 sites x 8 float4 of xc
        int ss = tid >> 3, q = tid & 7;
        sXc4[ss][q] = reinterpret_cast<const float4*>(xc + (blockIdx.x * 4 + ss) * NG)[q];
    }
    __syncthreads();

    const float4* fw4 = reinterpret_cast<const float4*>(fc_w);
    const float4  xq  = sXc4[si][lane & 7];
    const int     b0  = w2 * 256 + lane;
    #pragma unroll 2
    for (int c = 0; c < 8; ++c) {
        float4 v[8];
        #pragma unroll
        for (int p = 0; p < 8; ++p) v[p] = fw4[c * 512 + b0 + p * 32];
        #pragma unroll
        for (int p = 0; p < 8; ++p) {
            float pr = v[p].x * xq.x + v[p].y * xq.y + v[p].z * xq.z + v[p].w * xq.w;
            pr += __shfl_xor_sync(0xffffffffu, pr, 4);
            pr += __shfl_xor_sync(0xffffffffu, pr, 2);
            pr += __shfl_xor_sync(0xffffffffu, pr, 1);
            if ((lane & 7) == 0)
                sW[si][c * 64 + w2 * 32 + p * 4 + (lane >> 3)] = pr;
        }
    }
    if (w2 == 1) {                     // qb row j = 513
        float4 v = fw4[513 * 8 + (lane & 7)];
        float pr = v.x * xq.x + v.y * xq.y + v.z * xq.z + v.w * xq.w;
        pr += __shfl_xor_sync(0xffffffffu, pr, 4);
        pr += __shfl_xor_sync(0xffffffffu, pr, 2);
        pr += __shfl_xor_sync(0xffffffffu, pr, 1);
        if (lane == 0)
            g_qb[s] = fmaxf(pr + fc_b[513], 0.0f) * (1.0f / 64.0f);
    }
    __syncthreads();

    // activations: thread h = w2*32 + lane of site si
    const int h = w2 * 32 + lane;
    float wv[8];
    #pragma unroll
    for (int c = 0; c < 8; ++c) wv[c] = sW[si][c * 64 + h] + fc_b[c * NH + h];

    float gm   = expf(wv[0]) + 1.0f;
    float nge  = -2.0f * sigm(wv[1]);
    float go   = sigm(wv[2]);
    float gl   = expf(2.0f * wv[3]);
    float araw = wv[4];
    float gb   = sigm(wv[5]);
    float kb   = sigm(wv[6]) * 0.1f;
    float gi   = sigm(wv[7]);

    // softmax over the site's 64 h (2 warps)
    float m = araw;
    #pragma unroll
    for (int o = 16; o; o >>= 1) m = fmaxf(m, __shfl_xor_sync(0xffffffffu, m, o));
    if (lane == 0) sMax[si][w2] = m;
    __syncthreads();
    m = fmaxf(sMax[si][0], sMax[si][1]);
    float e = expf(araw - m);
    float ssum = e;
    #pragma unroll
    for (int o = 16; o; o >>= 1) ssum += __shfl_xor_sync(0xffffffffu, ssum, o);
    if (lane == 0) sSum[si][w2] = ssum;
    __syncthreads();
    float ga = e / (sSum[si][0] + sSum[si][1]);

    float* base = g_c + s * NK * NH;
    base[0 * NH + h] = gm;
    base[1 * NH + h] = nge;
    base[2 * NH + h] = go;
    base[3 * NH + h] = gl;
    base[4 * NH + h] = ga;
    base[5 * NH + h] = go * (1.0f - gb) * ga - ga;   // chc
    base[6 * NH + h] = kb * ga;                      // cg
    base[7 * NH + h] = go * gb;                      // gogb
    base[8 * NH + h] = 1.0f - kb;                    // kb1
    base[9 * NH + h] = gi;
}

// ---------------------------------------------------------------------------
// Scan: 1024 blocks x 64 threads. The two warps are INDEPENDENT after the
// prologue: warp0 owns h=0..31 -> g_pA, warp1 owns h=32..63 -> g_pB.
// Zero in-loop __syncthreads. Per step ~17 ops; per chunk: burst STS to a
// private double-buffered pitch-36 region, 1 __syncwarp, float4 transpose-
// reduce (2 lanes per t), 1 shfl, predicated scatter STG (hidden).
// Staging precomputes ReLU(Ta) into .z (gm>1 lets max move out of the loop).
// ---------------------------------------------------------------------------
__global__ void __launch_bounds__(64)
scan_kernel(const float* __restrict__ x) {
    __shared__ float4 sForc[NTP];                 // 5888 B
    __shared__ float  sBuf[2][2][CH * RPITCH];    // 9216 B  [warp][parity]

    const int tid  = threadIdx.x;
    const int warp = tid >> 5;
    const int lane = tid & 31;
    const int s    = blockIdx.x;

    // constants for h = tid (warp0: 0..31, warp1: 32..63)
    const float* base = g_c + s * NK * NH;
    const float gm   = base[0 * NH + tid];
    const float nge  = base[1 * NH + tid];
    const float go   = base[2 * NH + tid];
    const float gl   = base[3 * NH + tid];
    const float ga   = base[4 * NH + tid];
    const float chc  = base[5 * NH + tid];
    const float cg   = base[6 * NH + tid];
    const float gogb = base[7 * NH + tid];
    const float kb1  = base[8 * NH + tid];
    const float gi   = base[9 * NH + tid];

    // stage forcing + rain/snow partition; .z = ReLU(Ta)
    const float4* x4 = reinterpret_cast<const float4*>(x);
    for (int t = tid; t < NTP; t += 64) {
        float4 o = make_float4(0.f, 0.f, 0.f, 0.f);
        if (t < NT) {
            float4 xi = x4[t * NS + s];
            float P = xi.x, E = xi.y, T1 = xi.z, T2 = xi.w;
            float Ta = (T1 + T2) * 0.5f;
            bool valid  = (T1 < 0.0f) && (T2 > 0.0f);
            float denom = valid ? (T2 - T1) : 1.0f;
            float ratio = valid ? (T1 + T2) / denom : 0.0f;
            ratio = fminf(fmaxf(ratio, -0.999999f), 0.999999f);
            float rP = 1.0f - acosf(ratio) / 3.1415f;
            if (T1 >= 0.0f) rP = 1.0f;
            if (T2 <= 0.0f) rP = 0.0f;
            o.x = (1.0f - rP) * P;       // Ps
            o.y = rP * P;                // Pl
            o.z = fmaxf(Ta, 0.0f);       // ReLU(Ta)  (mt = gm * this)
            o.w = E;
        }
        sForc[t] = o;
    }
    __syncthreads();                    // the ONLY block-wide barrier

    float* outHalf = (warp == 0) ? g_pA : g_pB;
    const int rt = lane >> 1;           // reduce: 2 lanes per timestep
    const int rq = lane & 1;

    float S0 = 0.0f, H0 = 0.0f, G0 = 0.0f;

    for (int c = 0; c < NCHUNK; ++c) {
        float* buf = sBuf[warp][c & 1];
        const float4* fp = sForc + c * CH;
        float yv[CH];
        #pragma unroll
        for (int tt = 0; tt < CH; ++tt) {
            float4 f  = fp[tt];                      // broadcast LDS.128
            float Sm  = fminf(S0, f.z * gm);
            float At  = fmaf(f.w, nge, f.y * gi);    // Pl*gi - E*ge
            float H   = fmaxf(H0 + Sm + At, 0.0f);
            float Hc  = fminf(H, gl);
            float t1  = fmaf(-go, Hc, H);
            float g2  = fmaf(Hc, gogb, G0);
            H0 = fminf(t1, gl);
            G0 = g2 * kb1;
            S0 = (S0 - Sm) + f.x;
            float y = H * ga;
            y = fmaf(Hc, chc, y);
            y = fmaf(g2, cg, y);
            yv[tt] = y;
        }
        #pragma unroll
        for (int tt = 0; tt < CH; ++tt)
            buf[tt * RPITCH + lane] = yv[tt];        // burst, conflict-free
        __syncwarp();
        // transpose-reduce: lane pair (rt, rq); pitch-36 float4 reads are
        // conflict-free (each quarter-warp spans all 32 banks)
        const float4* rr = reinterpret_cast<const float4*>(buf + rt * RPITCH + rq * 16);
        float4 v0 = rr[0], v1 = rr[1], v2 = rr[2], v3 = rr[3];
        float p = (((v0.x + v0.y) + (v0.z + v0.w)) + ((v1.x + v1.y) + (v1.z + v1.w)))
                + (((v2.x + v2.y) + (v2.z + v2.w)) + ((v3.x + v3.y) + (v3.z + v3.w)));
        p += __shfl_xor_sync(0xffffffffu, p, 1);
        const int tg = c * CH + rt;
        if (rq == 0 && tg < NT) outHalf[tg * NS + s] = p;
    }
}

// ---------------------------------------------------------------------------
// Combine: out[t][s] = pA + pB + qb[s], fully coalesced float4.
// Grid 365 x 256 covers NT*NS/4 exactly.
// ---------------------------------------------------------------------------
__global__ void __launch_bounds__(256)
combine_kernel(float* __restrict__ out) {
    const int idx = blockIdx.x * 256 + threadIdx.x;   // 0 .. NT*NS/4-1
    const int s4  = idx & 255;                        // NS/4 = 256
    float4 a = reinterpret_cast<const float4*>(g_pA)[idx];
    float4 b = reinterpret_cast<const float4*>(g_pB)[idx];
    float4 q = reinterpret_cast<const float4*>(g_qb)[s4];
    float4 o;
    o.x = a.x + b.x + q.x;
    o.y = a.y + b.y + q.y;
    o.z = a.z + b.z + q.z;
    o.w = a.w + b.w + q.w;
    reinterpret_cast<float4*>(out)[idx] = o;
}

// ---------------------------------------------------------------------------
extern "C" void kernel_launch(void* const* d_in, const int* in_sizes, int n_in,
                              void* d_out, int out_size) {
    const float* x    = (const float*)d_in[0];   // [NT, NS, 4]
    const float* xc   = (const float*)d_in[1];   // [NS, NG]
    const float* fc_w = (const float*)d_in[2];   // [NW, NG]
    const float* fc_b = (const float*)d_in[3];   // [NW]
    float* out = (float*)d_out;                  // [NT, NS]

    gates_kernel<<<NS / 4, 256>>>(xc, fc_w, fc_b);
    scan_kernel<<<NS, 64>>>(x);
    combine_kernel<<<NT, 256>>>(out);
}

// round 10
// speedup vs baseline: 1.3481x; 1.1079x over previous
#include <cuda_runtime.h>
#include <math.h>

#define NT 365
#define NTP 368          // 23 chunks of 16
#define NCHUNK 23
#define CH 16
#define RPITCH 36        // reduce-buffer row pitch (conflict-free float4 reads)
#define NS 1024
#define NH 64
#define NG 32
#define NW 514           // NH*8 + 2
#define WPITCH 520       // g_w row pitch (16B-aligned rows)

__device__ float g_w[NS * WPITCH];   // pre-activations w[s][j]
__device__ float g_pA[NT * NS];      // partial Y, h in [0,32)
__device__ float g_pB[NT * NS];      // partial Y, h in [32,64)

__device__ __forceinline__ float sigm(float x) { return 1.0f / (1.0f + expf(-x)); }

// ---------------------------------------------------------------------------
// GEMM: w[s][j] = xc[s,:] . fc_w[j,:] + fc_b[j].
// Grid 144 = 16 site-tiles x 9 row-tiles; 256 threads; thread computes 4x4.
// Tiles staged transposed (pitch 68 -> 16B-aligned rows, mild staging
// conflicts only). Inner k-step: 2 x LDS.128 + 16 FFMA.
// fc_w read ONCE per row-tile per site-tile: total L2 traffic ~0.6 MB.
// ---------------------------------------------------------------------------
__global__ void __launch_bounds__(256)
gemm_kernel(const float* __restrict__ xc,
            const float* __restrict__ fc_w,
            const float* __restrict__ fc_b) {
    __shared__ float sX[32 * 68];   // [k][site_loc]
    __shared__ float sF[32 * 68];   // [k][row_loc]

    const int t  = threadIdx.x;
    const int s0 = (blockIdx.x & 15) << 6;   // site tile base (16 tiles)
    const int j0 = (blockIdx.x >> 4) << 6;   // row  tile base (9 tiles)

    // stage both tiles transposed (coalesced global reads)
    #pragma unroll
    for (int i = 0; i < 8; ++i) {
        const int idx = t + (i << 8);
        const int k   = idx & 31;
        const int loc = idx >> 5;
        sX[k * 68 + loc] = xc[(s0 + loc) * NG + k];
        const int j = j0 + loc;
        sF[k * 68 + loc] = (j < NW) ? fc_w[j * NG + k] : 0.0f;
    }
    __syncthreads();

    const int tj = t & 15;          // row quad
    const int ts = t >> 4;          // site quad
    float acc[4][4];
    #pragma unroll
    for (int a = 0; a < 4; ++a)
        #pragma unroll
        for (int b = 0; b < 4; ++b) acc[a][b] = 0.0f;

    #pragma unroll
    for (int k = 0; k < 32; ++k) {
        const float4 xs = *reinterpret_cast<const float4*>(sX + k * 68 + (ts << 2));
        const float4 fj = *reinterpret_cast<const float4*>(sF + k * 68 + (tj << 2));
        const float xa[4] = {xs.x, xs.y, xs.z, xs.w};
        const float fb[4] = {fj.x, fj.y, fj.z, fj.w};
        #pragma unroll
        for (int a = 0; a < 4; ++a)
            #pragma unroll
            for (int b = 0; b < 4; ++b)
                acc[a][b] = fmaf(xa[a], fb[b], acc[a][b]);
    }

    // epilogue: + bias, guarded scalar stores (j < NW)
    float bias[4];
    #pragma unroll
    for (int b = 0; b < 4; ++b) {
        const int j = j0 + (tj << 2) + b;
        bias[b] = (j < NW) ? fc_b[j] : 0.0f;
    }
    #pragma unroll
    for (int a = 0; a < 4; ++a) {
        const int sg = s0 + (ts << 2) + a;
        #pragma unroll
        for (int b = 0; b < 4; ++b) {
            const int j = j0 + (tj << 2) + b;
            if (j < NW) g_w[sg * WPITCH + j] = acc[a][b] + bias[b];
        }
    }
}

// ---------------------------------------------------------------------------
// Scan: 1024 blocks x 64 threads. Prologue: read w row (coalesced), stage
// forcing (+acos, ReLU(Ta) prefolded), activations + cross-warp softmax.
// Loop: warps fully independent (warp0 -> g_pA, warp1 -> g_pB), zero
// block barriers; chunked y buffering + float4 transpose-reduce per warp.
// ---------------------------------------------------------------------------
__global__ void __launch_bounds__(64)
scan_kernel(const float* __restrict__ x) {
    __shared__ float4 sForc[NTP];                 // 5888 B
    __shared__ float  sBuf[2][2][CH * RPITCH];    // 9216 B  [warp][parity]
    __shared__ float  sMax[2], sSum[2];

    const int tid  = threadIdx.x;
    const int warp = tid >> 5;
    const int lane = tid & 31;
    const int s    = blockIdx.x;

    // ---- load this site's pre-activations (coalesced, 9 lines) ----
    const float* wrow = g_w + s * WPITCH;
    float wv[8];
    #pragma unroll
    for (int c = 0; c < 8; ++c) wv[c] = wrow[c * 64 + tid];
    const float qb = fmaxf(wrow[513], 0.0f) * (1.0f / 64.0f);

    // ---- stage forcing + rain/snow partition; .z = ReLU(Ta) ----
    const float4* x4 = reinterpret_cast<const float4*>(x);
    for (int t = tid; t < NTP; t += 64) {
        float4 o = make_float4(0.f, 0.f, 0.f, 0.f);
        if (t < NT) {
            float4 xi = x4[t * NS + s];
            float P = xi.x, E = xi.y, T1 = xi.z, T2 = xi.w;
            float Ta = (T1 + T2) * 0.5f;
            bool valid  = (T1 < 0.0f) && (T2 > 0.0f);
            float denom = valid ? (T2 - T1) : 1.0f;
            float ratio = valid ? (T1 + T2) / denom : 0.0f;
            ratio = fminf(fmaxf(ratio, -0.999999f), 0.999999f);
            float rP = 1.0f - acosf(ratio) / 3.1415f;
            if (T1 >= 0.0f) rP = 1.0f;
            if (T2 <= 0.0f) rP = 0.0f;
            o.x = (1.0f - rP) * P;       // Ps
            o.y = rP * P;                // Pl
            o.z = fmaxf(Ta, 0.0f);       // ReLU(Ta)
            o.w = E;
        }
        sForc[t] = o;
    }

    // ---- activations (h = tid) ----
    const float gm   = expf(wv[0]) + 1.0f;
    const float nge  = -2.0f * sigm(wv[1]);
    const float go   = sigm(wv[2]);
    const float gl   = expf(2.0f * wv[3]);
    const float araw = wv[4];
    const float gb   = sigm(wv[5]);
    const float kb   = sigm(wv[6]) * 0.1f;
    const float gi   = sigm(wv[7]);
    const float kb1  = 1.0f - kb;

    // ---- softmax over 64 h across the 2 warps ----
    float m = araw;
    #pragma unroll
    for (int o = 16; o; o >>= 1) m = fmaxf(m, __shfl_xor_sync(0xffffffffu, m, o));
    if (lane == 0) sMax[warp] = m;
    __syncthreads();
    m = fmaxf(sMax[0], sMax[1]);
    float e = expf(araw - m);
    float ssum = e;
    #pragma unroll
    for (int o = 16; o; o >>= 1) ssum += __shfl_xor_sync(0xffffffffu, ssum, o);
    if (lane == 0) sSum[warp] = ssum;
    __syncthreads();
    const float ga = e / (sSum[0] + sSum[1]);

    const float chc  = go * (1.0f - gb) * ga - ga;   // coeff of Hc in y
    const float cg   = kb * ga;                      // coeff of g2 in y
    const float gogb = go * gb;
    const float qbw  = (warp == 0) ? qb : 0.0f;      // qb folded into pA

    float* outHalf = (warp == 0) ? g_pA : g_pB;
    const int rt = lane >> 1;
    const int rq = lane & 1;

    float S0 = 0.0f, H0 = 0.0f, G0 = 0.0f;

    for (int c = 0; c < NCHUNK; ++c) {
        float* buf = sBuf[warp][c & 1];
        const float4* fp = sForc + c * CH;
        float yv[CH];
        #pragma unroll
        for (int tt = 0; tt < CH; ++tt) {
            float4 f  = fp[tt];                      // broadcast LDS.128
            float Sm  = fminf(S0, f.z * gm);
            float At  = fmaf(f.w, nge, f.y * gi);    // Pl*gi - E*ge
            float H   = fmaxf(H0 + Sm + At, 0.0f);
            float Hc  = fminf(H, gl);
            float t1  = fmaf(-go, Hc, H);
            float g2  = fmaf(Hc, gogb, G0);
            H0 = fminf(t1, gl);
            G0 = g2 * kb1;
            S0 = (S0 - Sm) + f.x;
            float y = H * ga;
            y = fmaf(Hc, chc, y);
            y = fmaf(g2, cg, y);
            yv[tt] = y;
        }
        #pragma unroll
        for (int tt = 0; tt < CH; ++tt)
            buf[tt * RPITCH + lane] = yv[tt];        // burst, conflict-free
        __syncwarp();
        const float4* rr = reinterpret_cast<const float4*>(buf + rt * RPITCH + rq * 16);
        float4 v0 = rr[0], v1 = rr[1], v2 = rr[2], v3 = rr[3];
        float p = (((v0.x + v0.y) + (v0.z + v0.w)) + ((v1.x + v1.y) + (v1.z + v1.w)))
                + (((v2.x + v2.y) + (v2.z + v2.w)) + ((v3.x + v3.y) + (v3.z + v3.w)));
        p += __shfl_xor_sync(0xffffffffu, p, 1);
        const int tg = c * CH + rt;
        if (rq == 0 && tg < NT) outHalf[tg * NS + s] = p + qbw;
    }
}

// ---------------------------------------------------------------------------
// Combine: out[t][s] = pA + pB  (qb already folded into pA). float4, coalesced.
// ---------------------------------------------------------------------------
__global__ void __launch_bounds__(256)
combine_kernel(float* __restrict__ out) {
    const int idx = blockIdx.x * 256 + threadIdx.x;   // NT*NS/4 elements
    float4 a = reinterpret_cast<const float4*>(g_pA)[idx];
    float4 b = reinterpret_cast<const float4*>(g_pB)[idx];
    float4 o;
    o.x = a.x + b.x;
    o.y = a.y + b.y;
    o.z = a.z + b.z;
    o.w = a.w + b.w;
    reinterpret_cast<float4*>(out)[idx] = o;
}

// ---------------------------------------------------------------------------
extern "C" void kernel_launch(void* const* d_in, const int* in_sizes, int n_in,
                              void* d_out, int out_size) {
    const float* x    = (const float*)d_in[0];   // [NT, NS, 4]
    const float* xc   = (const float*)d_in[1];   // [NS, NG]
    const float* fc_w = (const float*)d_in[2];   // [NW, NG]
    const float* fc_b = (const float*)d_in[3];   // [NW]
    float* out = (float*)d_out;                  // [NT, NS]

    gemm_kernel<<<16 * 9, 256>>>(xc, fc_w, fc_b);
    scan_kernel<<<NS, 64>>>(x);
    combine_kernel<<<NT, 256>>>(out);
}